// round 7
// baseline (speedup 1.0000x reference)
#include <cuda_runtime.h>
#include <math.h>
#include <stdint.h>

// Problem constants
#define Bb   2
#define Ss   2048
#define Dd   1024
#define NHh  16
#define HDd  64
#define MM   (Bb*Ss)
#define PLANE (Ss*Ss)
#define BSD  (Bb*Ss*Dd)

// ---------------- scratch (device globals) ----------------
__device__ float g_Q[BSD];
__device__ float g_K[BSD];
__device__ float g_V[BSD];
__device__ float g_Qh[BSD];    // [b,h,s,d]
__device__ float g_Kh[BSD];
__device__ float g_Vh[BSD];
__device__ float g_AH[BSD];    // attn out per head [b,h,s,d]
__device__ float g_A[BSD];     // merged [b,s,D]
__device__ float g_Sc[134217728];  // normalized probs, per-head layout [b,h,l,n]

// ---------------------------------------------------------------------------
// tf32 helpers
// ---------------------------------------------------------------------------
__device__ __forceinline__ uint32_t f2tf(float f) {
    uint32_t u;
    asm("cvt.rna.tf32.f32 %0, %1;" : "=r"(u) : "f"(f));
    return u;
}

__device__ __forceinline__ void mma_tf32(float* c, const uint32_t* a, const uint32_t* b) {
    asm volatile(
        "mma.sync.aligned.m16n8k8.row.col.f32.tf32.tf32.f32 "
        "{%0,%1,%2,%3}, {%4,%5,%6,%7}, {%8,%9}, {%0,%1,%2,%3};\n"
        : "+f"(c[0]), "+f"(c[1]), "+f"(c[2]), "+f"(c[3])
        : "r"(a[0]), "r"(a[1]), "r"(a[2]), "r"(a[3]), "r"(b[0]), "r"(b[1]));
}

// ---------------------------------------------------------------------------
// Projection GEMM (tf32): C[M,1024] = A[M,1024] @ W[1024,1024] + bias
// ---------------------------------------------------------------------------
__global__ __launch_bounds__(256) void gemm_tf32_bias(
    const float* __restrict__ A, const float* __restrict__ W,
    const float* __restrict__ bias, float* __restrict__ C)
{
    __shared__ uint32_t As[128][36];
    __shared__ uint32_t Bs[32][136];
    const int tid  = threadIdx.x;
    const int lane = tid & 31, w = tid >> 5;
    const int g = lane >> 2, tg = lane & 3;
    const int bm = blockIdx.y * 128, bn = blockIdx.x * 128;
    const int warpM = (w >> 2) * 64, warpN = (w & 3) * 32;

    float acc[4][4][4];
#pragma unroll
    for (int mt = 0; mt < 4; ++mt)
#pragma unroll
        for (int nt = 0; nt < 4; ++nt)
#pragma unroll
            for (int i = 0; i < 4; ++i) acc[mt][nt][i] = 0.f;

    for (int k0 = 0; k0 < Dd; k0 += 32) {
#pragma unroll
        for (int it = 0; it < 4; ++it) {
            int ch = tid + it * 256;
            int m = ch >> 3, kq = (ch & 7) << 2;
            float4 v = *(const float4*)(A + (size_t)(bm + m) * Dd + k0 + kq);
            uint4 u = {f2tf(v.x), f2tf(v.y), f2tf(v.z), f2tf(v.w)};
            *(uint4*)&As[m][kq] = u;
        }
#pragma unroll
        for (int it = 0; it < 4; ++it) {
            int ch = tid + it * 256;
            int kk = ch >> 5, n4 = (ch & 31) << 2;
            float4 v = *(const float4*)(W + (size_t)(k0 + kk) * Dd + bn + n4);
            uint4 u = {f2tf(v.x), f2tf(v.y), f2tf(v.z), f2tf(v.w)};
            *(uint4*)&Bs[kk][n4] = u;
        }
        __syncthreads();
#pragma unroll
        for (int ks = 0; ks < 32; ks += 8) {
            uint32_t af[4][4], bf[4][2];
#pragma unroll
            for (int mt = 0; mt < 4; ++mt) {
                int r = warpM + mt * 16 + g;
                af[mt][0] = As[r][ks + tg];
                af[mt][1] = As[r + 8][ks + tg];
                af[mt][2] = As[r][ks + tg + 4];
                af[mt][3] = As[r + 8][ks + tg + 4];
            }
#pragma unroll
            for (int nt = 0; nt < 4; ++nt) {
                int c = warpN + nt * 8 + g;
                bf[nt][0] = Bs[ks + tg][c];
                bf[nt][1] = Bs[ks + tg + 4][c];
            }
#pragma unroll
            for (int mt = 0; mt < 4; ++mt)
#pragma unroll
                for (int nt = 0; nt < 4; ++nt)
                    mma_tf32(acc[mt][nt], af[mt], bf[nt]);
        }
        __syncthreads();
    }
#pragma unroll
    for (int mt = 0; mt < 4; ++mt)
#pragma unroll
        for (int nt = 0; nt < 4; ++nt) {
            int r0 = bm + warpM + mt * 16 + g;
            int c0 = bn + warpN + nt * 8 + 2 * tg;
            float b0 = bias[c0], b1 = bias[c0 + 1];
            float2 v0 = {acc[mt][nt][0] + b0, acc[mt][nt][1] + b1};
            float2 v1 = {acc[mt][nt][2] + b0, acc[mt][nt][3] + b1};
            *(float2*)(C + (size_t)r0 * Dd + c0) = v0;
            *(float2*)(C + (size_t)(r0 + 8) * Dd + c0) = v1;
        }
}

// ---------------------------------------------------------------------------
// Head split: out[b][h][s][d] = in[b][s][d*16+h]
// ---------------------------------------------------------------------------
__global__ __launch_bounds__(256) void head_split_kernel(
    const float* __restrict__ in, float* __restrict__ out)
{
    int i = blockIdx.x * 256 + threadIdx.x;
    int d  = i & 63;
    int s  = (i >> 6) & 2047;
    int hb = i >> 17;
    int h  = hb & 15;
    int b  = hb >> 4;
    out[i] = in[(size_t)(b*2048 + s) * 1024 + d*16 + h];
}

// ---------------------------------------------------------------------------
// FUSED scores + head-softmax.
// Block tile: 32(l) x 32(n), all 16 heads. 8 warps (2l x 4n), warp tile 16x8.
// Per thread: acc[16][4] (16 heads x 4 accum). Loops heads through smem tiles.
// Softmax over h happens entirely in registers; writes:
//   - probs in [b,l,n,h] layout (d_out)
//   - normalized P in per-head [b,h,l,n] layout (g_Sc) for the attn*V GEMM
// ---------------------------------------------------------------------------
__global__ __launch_bounds__(256) void fused_scores_softmax(float* __restrict__ probs)
{
    __shared__ uint32_t Qs[32][68];   // [l][d], pad 68: frag banks (4g+tg) distinct
    __shared__ uint32_t Ks[32][68];   // [n][d]
    const int tid  = threadIdx.x;
    const int lane = tid & 31, w = tid >> 5;
    const int g = lane >> 2, tg = lane & 3;
    const int b  = blockIdx.z;
    const int bm = blockIdx.y * 32;   // l
    const int bn = blockIdx.x * 32;   // n
    const int warpM = (w >> 2) * 16, warpN = (w & 3) * 8;

    float acc[16][4];
#pragma unroll
    for (int h = 0; h < 16; ++h)
#pragma unroll
        for (int i = 0; i < 4; ++i) acc[h][i] = 0.f;

    const int row = tid >> 4;            // 0..31 when combined with 2 iters? (512 f4 total)
    // 32x64 floats = 512 float4; 256 threads -> 2 per thread.
#pragma unroll 1
    for (int h = 0; h < 16; ++h) {
        const float* Q  = g_Qh + (size_t)(b * 16 + h) * (Ss * HDd);
        const float* Kp = g_Kh + (size_t)(b * 16 + h) * (Ss * HDd);
#pragma unroll
        for (int it = 0; it < 2; ++it) {
            int ch = tid + it * 256;          // 0..511
            int r = ch >> 4, c4 = (ch & 15) << 2;
            float4 qv = *(const float4*)(Q  + (size_t)(bm + r) * HDd + c4);
            float4 kv = *(const float4*)(Kp + (size_t)(bn + r) * HDd + c4);
            uint4 qu = {f2tf(qv.x), f2tf(qv.y), f2tf(qv.z), f2tf(qv.w)};
            uint4 ku = {f2tf(kv.x), f2tf(kv.y), f2tf(kv.z), f2tf(kv.w)};
            *(uint4*)&Qs[r][c4] = qu;
            *(uint4*)&Ks[r][c4] = ku;
        }
        __syncthreads();
#pragma unroll
        for (int ks = 0; ks < 64; ks += 8) {
            uint32_t af[4], bf[2];
            af[0] = Qs[warpM + g][ks + tg];
            af[1] = Qs[warpM + g + 8][ks + tg];
            af[2] = Qs[warpM + g][ks + tg + 4];
            af[3] = Qs[warpM + g + 8][ks + tg + 4];
            bf[0] = Ks[warpN + g][ks + tg];
            bf[1] = Ks[warpN + g][ks + tg + 4];
            mma_tf32(acc[h], af, bf);
        }
        __syncthreads();
    }

    // Softmax over the 16 heads, per accumulator position.
#pragma unroll
    for (int p = 0; p < 4; ++p) {
        int l = bm + warpM + g + ((p >> 1) << 3);
        int n = bn + warpN + 2 * tg + (p & 1);
        float e[16];
        float m = -1e30f;
#pragma unroll
        for (int h = 0; h < 16; ++h) {
            float s = 0.125f * acc[h][p];
            e[h] = s;
            m = fmaxf(m, s);
        }
        float sum = 0.f;
#pragma unroll
        for (int h = 0; h < 16; ++h) { e[h] = __expf(e[h] - m); sum += e[h]; }
        float r = 1.0f / sum;

        float* po = probs + ((size_t)((b * 2048 + l) * 2048 + n)) * 16;
#pragma unroll
        for (int h4 = 0; h4 < 16; h4 += 4) {
            float4 o = {e[h4]*r, e[h4+1]*r, e[h4+2]*r, e[h4+3]*r};
            *(float4*)(po + h4) = o;
        }
        size_t off = (size_t)l * Ss + n;
#pragma unroll
        for (int h = 0; h < 16; ++h)
            g_Sc[(size_t)(b * 16 + h) * PLANE + off] = e[h] * r;
    }
}

// ---------------------------------------------------------------------------
// Attn*V (tf32): per plane z: O[l,d] = sum_n P[l,n] * V[n,d]
// M=2048, N=64, K=2048. Block 128x64, BK=32, 256 threads, 8 warps (4m x 2n).
// ---------------------------------------------------------------------------
__global__ __launch_bounds__(256) void attnv_tf32()
{
    __shared__ uint32_t As[128][36];
    __shared__ uint32_t Bs[32][72];
    const int tid  = threadIdx.x;
    const int lane = tid & 31, w = tid >> 5;
    const int g = lane >> 2, tg = lane & 3;
    const int z  = blockIdx.y;
    const int bm = blockIdx.x * 128;
    const int warpM = (w >> 1) * 32, warpN = (w & 1) * 32;
    const float* P = g_Sc + (size_t)z * PLANE;
    const float* V = g_Vh + (size_t)z * (Ss*HDd);
    float* O = g_AH + (size_t)z * (Ss*HDd);

    float acc[2][4][4];
#pragma unroll
    for (int mt = 0; mt < 2; ++mt)
#pragma unroll
        for (int nt = 0; nt < 4; ++nt)
#pragma unroll
            for (int i = 0; i < 4; ++i) acc[mt][nt][i] = 0.f;

    for (int k0 = 0; k0 < Ss; k0 += 32) {
#pragma unroll
        for (int it = 0; it < 4; ++it) {
            int ch = tid + it * 256;
            int m = ch >> 3, kq = (ch & 7) << 2;
            float4 v = *(const float4*)(P + (size_t)(bm + m) * Ss + k0 + kq);
            uint4 u = {f2tf(v.x), f2tf(v.y), f2tf(v.z), f2tf(v.w)};
            *(uint4*)&As[m][kq] = u;
        }
#pragma unroll
        for (int it = 0; it < 2; ++it) {
            int ch = tid + it * 256;
            int kk = ch >> 4, n4 = (ch & 15) << 2;
            float4 v = *(const float4*)(V + (size_t)(k0 + kk) * HDd + n4);
            uint4 u = {f2tf(v.x), f2tf(v.y), f2tf(v.z), f2tf(v.w)};
            *(uint4*)&Bs[kk][n4] = u;
        }
        __syncthreads();
#pragma unroll
        for (int ks = 0; ks < 32; ks += 8) {
            uint32_t af[2][4], bf[4][2];
#pragma unroll
            for (int mt = 0; mt < 2; ++mt) {
                int r = warpM + mt * 16 + g;
                af[mt][0] = As[r][ks + tg];
                af[mt][1] = As[r + 8][ks + tg];
                af[mt][2] = As[r][ks + tg + 4];
                af[mt][3] = As[r + 8][ks + tg + 4];
            }
#pragma unroll
            for (int nt = 0; nt < 4; ++nt) {
                int c = warpN + nt * 8 + g;
                bf[nt][0] = Bs[ks + tg][c];
                bf[nt][1] = Bs[ks + tg + 4][c];
            }
#pragma unroll
            for (int mt = 0; mt < 2; ++mt)
#pragma unroll
                for (int nt = 0; nt < 4; ++nt)
                    mma_tf32(acc[mt][nt], af[mt], bf[nt]);
        }
        __syncthreads();
    }
#pragma unroll
    for (int mt = 0; mt < 2; ++mt)
#pragma unroll
        for (int nt = 0; nt < 4; ++nt) {
            int r0 = bm + warpM + mt * 16 + g;
            int c0 = warpN + nt * 8 + 2 * tg;
            float2 v0 = {acc[mt][nt][0], acc[mt][nt][1]};
            float2 v1 = {acc[mt][nt][2], acc[mt][nt][3]};
            *(float2*)(O + (size_t)r0 * HDd + c0) = v0;
            *(float2*)(O + (size_t)(r0 + 8) * HDd + c0) = v1;
        }
}

// ---------------------------------------------------------------------------
// Head merge: g_A[b][s][d*16+h] = g_AH[b][h][s][d]
// ---------------------------------------------------------------------------
__global__ __launch_bounds__(256) void head_merge_kernel()
{
    int i = blockIdx.x * 256 + threadIdx.x;
    int j = i & 1023;
    int s = (i >> 10) & 2047;
    int b = i >> 21;
    int h = j & 15;
    int d = j >> 4;
    g_A[i] = g_AH[(size_t)((b*16 + h)*2048 + s) * 64 + d];
}

// ---------------------------------------------------------------------------
extern "C" void kernel_launch(void* const* d_in, const int* in_sizes, int n_in,
                              void* d_out, int out_size)
{
    const float* query = (const float*)d_in[0];
    const float* key   = (const float*)d_in[1];
    const float* value = (const float*)d_in[2];
    const float* Wq = (const float*)d_in[3];  const float* bq = (const float*)d_in[4];
    const float* Wk = (const float*)d_in[5];  const float* bk = (const float*)d_in[6];
    const float* Wv = (const float*)d_in[7];  const float* bv = (const float*)d_in[8];
    const float* Wo = (const float*)d_in[9];  const float* bo = (const float*)d_in[10];

    float* out   = (float*)d_out;
    float* probs = out + BSD;

    void* p;
    cudaGetSymbolAddress(&p, g_Q);  float* gQ  = (float*)p;
    cudaGetSymbolAddress(&p, g_K);  float* gK  = (float*)p;
    cudaGetSymbolAddress(&p, g_V);  float* gV  = (float*)p;
    cudaGetSymbolAddress(&p, g_Qh); float* gQh = (float*)p;
    cudaGetSymbolAddress(&p, g_Kh); float* gKh = (float*)p;
    cudaGetSymbolAddress(&p, g_Vh); float* gVh = (float*)p;
    cudaGetSymbolAddress(&p, g_A);  float* gA  = (float*)p;

    dim3 gemm_grid(Dd/128, MM/128);   // (8, 32)

    // 1) Projections (tf32 tensor cores)
    gemm_tf32_bias<<<gemm_grid, 256>>>(query, Wq, bq, gQ);
    gemm_tf32_bias<<<gemm_grid, 256>>>(key,   Wk, bk, gK);
    gemm_tf32_bias<<<gemm_grid, 256>>>(value, Wv, bv, gV);

    // 2) Head split into [b,h,s,d]
    head_split_kernel<<<BSD/256, 256>>>(gQ, gQh);
    head_split_kernel<<<BSD/256, 256>>>(gK, gKh);
    head_split_kernel<<<BSD/256, 256>>>(gV, gVh);

    // 3+4) Fused scores + head-softmax: writes probs (d_out) and per-head
    //      normalized P scratch (g_Sc)
    fused_scores_softmax<<<dim3(Ss/32, Ss/32, Bb), 256>>>(probs);

    // 5) Attn * V per head (tf32)
    attnv_tf32<<<dim3(Ss/128, Bb*NHh), 256>>>();

    // 6) Merge heads
    head_merge_kernel<<<BSD/256, 256>>>();

    // 7) Output projection (tf32)
    gemm_tf32_bias<<<gemm_grid, 256>>>(gA, Wo, bo, out);
}

// round 10
// speedup vs baseline: 1.0303x; 1.0303x over previous
#include <cuda_runtime.h>
#include <math.h>
#include <stdint.h>

// Problem constants
#define Bb   2
#define Ss   2048
#define Dd   1024
#define NHh  16
#define HDd  64
#define MM   (Bb*Ss)
#define PLANE (Ss*Ss)
#define BSD  (Bb*Ss*Dd)

// ---------------- scratch (device globals) ----------------
__device__ float g_Q[BSD];
__device__ float g_K[BSD];
__device__ float g_V[BSD];
__device__ float g_Qh[BSD];    // [b,h,s,d]
__device__ float g_Kh[BSD];
__device__ float g_Vh[BSD];
__device__ float g_AH[BSD];    // attn out per head [b,h,s,d]
__device__ float g_A[BSD];     // merged [b,s,D]
__device__ float g_Sc[134217728];  // normalized probs, per-head layout [b,h,l,n]

// ---------------------------------------------------------------------------
// tf32 helpers
// ---------------------------------------------------------------------------
__device__ __forceinline__ uint32_t f2tf(float f) {
    uint32_t u;
    asm("cvt.rna.tf32.f32 %0, %1;" : "=r"(u) : "f"(f));
    return u;
}

__device__ __forceinline__ void mma_tf32(float* c, const uint32_t* a, const uint32_t* b) {
    asm volatile(
        "mma.sync.aligned.m16n8k8.row.col.f32.tf32.tf32.f32 "
        "{%0,%1,%2,%3}, {%4,%5,%6,%7}, {%8,%9}, {%0,%1,%2,%3};\n"
        : "+f"(c[0]), "+f"(c[1]), "+f"(c[2]), "+f"(c[3])
        : "r"(a[0]), "r"(a[1]), "r"(a[2]), "r"(a[3]), "r"(b[0]), "r"(b[1]));
}

// ---------------------------------------------------------------------------
// Projection GEMM (tf32): C[M,1024] = A[M,1024] @ W[1024,1024] + bias
// ---------------------------------------------------------------------------
__global__ __launch_bounds__(256) void gemm_tf32_bias(
    const float* __restrict__ A, const float* __restrict__ W,
    const float* __restrict__ bias, float* __restrict__ C)
{
    __shared__ uint32_t As[128][36];
    __shared__ uint32_t Bs[32][136];
    const int tid  = threadIdx.x;
    const int lane = tid & 31, w = tid >> 5;
    const int g = lane >> 2, tg = lane & 3;
    const int bm = blockIdx.y * 128, bn = blockIdx.x * 128;
    const int warpM = (w >> 2) * 64, warpN = (w & 3) * 32;

    float acc[4][4][4];
#pragma unroll
    for (int mt = 0; mt < 4; ++mt)
#pragma unroll
        for (int nt = 0; nt < 4; ++nt)
#pragma unroll
            for (int i = 0; i < 4; ++i) acc[mt][nt][i] = 0.f;

    for (int k0 = 0; k0 < Dd; k0 += 32) {
#pragma unroll
        for (int it = 0; it < 4; ++it) {
            int ch = tid + it * 256;
            int m = ch >> 3, kq = (ch & 7) << 2;
            float4 v = *(const float4*)(A + (size_t)(bm + m) * Dd + k0 + kq);
            uint4 u = {f2tf(v.x), f2tf(v.y), f2tf(v.z), f2tf(v.w)};
            *(uint4*)&As[m][kq] = u;
        }
#pragma unroll
        for (int it = 0; it < 4; ++it) {
            int ch = tid + it * 256;
            int kk = ch >> 5, n4 = (ch & 31) << 2;
            float4 v = *(const float4*)(W + (size_t)(k0 + kk) * Dd + bn + n4);
            uint4 u = {f2tf(v.x), f2tf(v.y), f2tf(v.z), f2tf(v.w)};
            *(uint4*)&Bs[kk][n4] = u;
        }
        __syncthreads();
#pragma unroll
        for (int ks = 0; ks < 32; ks += 8) {
            uint32_t af[4][4], bf[4][2];
#pragma unroll
            for (int mt = 0; mt < 4; ++mt) {
                int r = warpM + mt * 16 + g;
                af[mt][0] = As[r][ks + tg];
                af[mt][1] = As[r + 8][ks + tg];
                af[mt][2] = As[r][ks + tg + 4];
                af[mt][3] = As[r + 8][ks + tg + 4];
            }
#pragma unroll
            for (int nt = 0; nt < 4; ++nt) {
                int c = warpN + nt * 8 + g;
                bf[nt][0] = Bs[ks + tg][c];
                bf[nt][1] = Bs[ks + tg + 4][c];
            }
#pragma unroll
            for (int mt = 0; mt < 4; ++mt)
#pragma unroll
                for (int nt = 0; nt < 4; ++nt)
                    mma_tf32(acc[mt][nt], af[mt], bf[nt]);
        }
        __syncthreads();
    }
#pragma unroll
    for (int mt = 0; mt < 4; ++mt)
#pragma unroll
        for (int nt = 0; nt < 4; ++nt) {
            int r0 = bm + warpM + mt * 16 + g;
            int c0 = bn + warpN + nt * 8 + 2 * tg;
            float b0 = bias[c0], b1 = bias[c0 + 1];
            float2 v0 = {acc[mt][nt][0] + b0, acc[mt][nt][1] + b1};
            float2 v1 = {acc[mt][nt][2] + b0, acc[mt][nt][3] + b1};
            *(float2*)(C + (size_t)r0 * Dd + c0) = v0;
            *(float2*)(C + (size_t)(r0 + 8) * Dd + c0) = v1;
        }
}

// ---------------------------------------------------------------------------
// Head split: out[b][h][s][d] = in[b][s][d*16+h]
// ---------------------------------------------------------------------------
__global__ __launch_bounds__(256) void head_split_kernel(
    const float* __restrict__ in, float* __restrict__ out)
{
    int i = blockIdx.x * 256 + threadIdx.x;
    int d  = i & 63;
    int s  = (i >> 6) & 2047;
    int hb = i >> 17;
    int h  = hb & 15;
    int b  = hb >> 4;
    out[i] = in[(size_t)(b*2048 + s) * 1024 + d*16 + h];
}

// ---------------------------------------------------------------------------
// FUSED scores + head-softmax, big tiles.
// Block: 64(l) x 32(n) x all 16 heads. 8 warps as 4(l) x 2(n); warp 16x16.
// acc[16][2][4] per thread. Per head: load Q 64x64 + K 32x64 (full HD=64).
// Epilogue: softmax over h in registers; probs written as 64B chunks;
// g_Sc writeback staged through smem for coalesced per-head 64x32 tiles.
// ---------------------------------------------------------------------------
__global__ __launch_bounds__(256) void fused_scores_softmax(float* __restrict__ probs)
{
    __shared__ uint32_t Qs[64][68];   // pad 68 == 4 (mod 32): frag banks 4g+tg distinct
    __shared__ uint32_t Ks[32][68];
    __shared__ float    Pst[64][33];  // writeback staging
    const int tid  = threadIdx.x;
    const int lane = tid & 31, w = tid >> 5;
    const int g = lane >> 2, tg = lane & 3;
    const int b  = blockIdx.z;
    const int bm = blockIdx.y * 64;   // l
    const int bn = blockIdx.x * 32;   // n
    const int warpM = (w >> 1) * 16;  // 4 warps over l
    const int warpN = (w & 1) * 16;   // 2 warps over n

    float acc[16][2][4];
#pragma unroll
    for (int h = 0; h < 16; ++h)
#pragma unroll
        for (int nt = 0; nt < 2; ++nt)
#pragma unroll
            for (int i = 0; i < 4; ++i) acc[h][nt][i] = 0.f;

#pragma unroll 1
    for (int h = 0; h < 16; ++h) {
        const float* Q  = g_Qh + (size_t)(b * 16 + h) * (Ss * HDd);
        const float* Kp = g_Kh + (size_t)(b * 16 + h) * (Ss * HDd);
        // Q tile 64x64 floats = 1024 float4, 4 per thread
#pragma unroll
        for (int it = 0; it < 4; ++it) {
            int ch = tid + it * 256;
            int r = ch >> 4, c4 = (ch & 15) << 2;
            float4 qv = *(const float4*)(Q + (size_t)(bm + r) * HDd + c4);
            uint4 qu = {f2tf(qv.x), f2tf(qv.y), f2tf(qv.z), f2tf(qv.w)};
            *(uint4*)&Qs[r][c4] = qu;
        }
        // K tile 32x64 floats = 512 float4, 2 per thread
#pragma unroll
        for (int it = 0; it < 2; ++it) {
            int ch = tid + it * 256;
            int r = ch >> 4, c4 = (ch & 15) << 2;
            float4 kv = *(const float4*)(Kp + (size_t)(bn + r) * HDd + c4);
            uint4 ku = {f2tf(kv.x), f2tf(kv.y), f2tf(kv.z), f2tf(kv.w)};
            *(uint4*)&Ks[r][c4] = ku;
        }
        __syncthreads();
#pragma unroll
        for (int ks = 0; ks < 64; ks += 8) {
            uint32_t af[4];
            af[0] = Qs[warpM + g][ks + tg];
            af[1] = Qs[warpM + g + 8][ks + tg];
            af[2] = Qs[warpM + g][ks + tg + 4];
            af[3] = Qs[warpM + g + 8][ks + tg + 4];
#pragma unroll
            for (int nt = 0; nt < 2; ++nt) {
                uint32_t bf[2];
                bf[0] = Ks[warpN + nt * 8 + g][ks + tg];
                bf[1] = Ks[warpN + nt * 8 + g][ks + tg + 4];
                mma_tf32(acc[h][nt], af, bf);
            }
        }
        __syncthreads();
    }

    // Softmax over the 16 heads at each of the 8 (l,n) positions this thread
    // owns; write probs (64B chunks) and overwrite acc with normalized values.
#pragma unroll
    for (int nt = 0; nt < 2; ++nt) {
#pragma unroll
        for (int i = 0; i < 4; ++i) {
            int l = bm + warpM + g + ((i >> 1) << 3);
            int n = bn + warpN + nt * 8 + 2 * tg + (i & 1);
            float e[16];
            float m = -1e30f;
#pragma unroll
            for (int h = 0; h < 16; ++h) {
                float s = 0.125f * acc[h][nt][i];
                e[h] = s;
                m = fmaxf(m, s);
            }
            float sum = 0.f;
#pragma unroll
            for (int h = 0; h < 16; ++h) { e[h] = __expf(e[h] - m); sum += e[h]; }
            float r = 1.0f / sum;
            float* po = probs + ((size_t)((b * 2048 + l) * 2048 + n)) * 16;
#pragma unroll
            for (int h4 = 0; h4 < 16; h4 += 4) {
                float4 o = {e[h4]*r, e[h4+1]*r, e[h4+2]*r, e[h4+3]*r};
                *(float4*)(po + h4) = o;
            }
#pragma unroll
            for (int h = 0; h < 16; ++h) acc[h][nt][i] = e[h] * r;
        }
    }

    // Staged coalesced writeback of normalized probs to per-head g_Sc planes.
    const int sr = tid >> 2;            // 0..63
    const int sc = (tid & 3) * 8;       // 0,8,16,24
#pragma unroll 1
    for (int h = 0; h < 16; ++h) {
        __syncthreads();
#pragma unroll
        for (int nt = 0; nt < 2; ++nt)
#pragma unroll
            for (int i = 0; i < 4; ++i) {
                int ll = warpM + g + ((i >> 1) << 3);
                int nn = warpN + nt * 8 + 2 * tg + (i & 1);
                Pst[ll][nn] = acc[h][nt][i];
            }
        __syncthreads();
        float* dst = g_Sc + (size_t)(b * 16 + h) * PLANE + (size_t)(bm + sr) * Ss + bn + sc;
        float4 o0 = {Pst[sr][sc+0], Pst[sr][sc+1], Pst[sr][sc+2], Pst[sr][sc+3]};
        float4 o1 = {Pst[sr][sc+4], Pst[sr][sc+5], Pst[sr][sc+6], Pst[sr][sc+7]};
        *(float4*)(dst)     = o0;
        *(float4*)(dst + 4) = o1;
    }
}

// ---------------------------------------------------------------------------
// Attn*V (tf32): per plane z: O[l,d] = sum_n P[l,n] * V[n,d]
// ---------------------------------------------------------------------------
__global__ __launch_bounds__(256) void attnv_tf32()
{
    __shared__ uint32_t As[128][36];
    __shared__ uint32_t Bs[32][72];
    const int tid  = threadIdx.x;
    const int lane = tid & 31, w = tid >> 5;
    const int g = lane >> 2, tg = lane & 3;
    const int z  = blockIdx.y;
    const int bm = blockIdx.x * 128;
    const int warpM = (w >> 1) * 32, warpN = (w & 1) * 32;
    const float* P = g_Sc + (size_t)z * PLANE;
    const float* V = g_Vh + (size_t)z * (Ss*HDd);
    float* O = g_AH + (size_t)z * (Ss*HDd);

    float acc[2][4][4];
#pragma unroll
    for (int mt = 0; mt < 2; ++mt)
#pragma unroll
        for (int nt = 0; nt < 4; ++nt)
#pragma unroll
            for (int i = 0; i < 4; ++i) acc[mt][nt][i] = 0.f;

    for (int k0 = 0; k0 < Ss; k0 += 32) {
#pragma unroll
        for (int it = 0; it < 4; ++it) {
            int ch = tid + it * 256;
            int m = ch >> 3, kq = (ch & 7) << 2;
            float4 v = *(const float4*)(P + (size_t)(bm + m) * Ss + k0 + kq);
            uint4 u = {f2tf(v.x), f2tf(v.y), f2tf(v.z), f2tf(v.w)};
            *(uint4*)&As[m][kq] = u;
        }
#pragma unroll
        for (int it = 0; it < 2; ++it) {
            int ch = tid + it * 256;
            int kk = ch >> 4, n4 = (ch & 15) << 2;
            float4 v = *(const float4*)(V + (size_t)(k0 + kk) * HDd + n4);
            uint4 u = {f2tf(v.x), f2tf(v.y), f2tf(v.z), f2tf(v.w)};
            *(uint4*)&Bs[kk][n4] = u;
        }
        __syncthreads();
#pragma unroll
        for (int ks = 0; ks < 32; ks += 8) {
            uint32_t af[2][4], bf[4][2];
#pragma unroll
            for (int mt = 0; mt < 2; ++mt) {
                int r = warpM + mt * 16 + g;
                af[mt][0] = As[r][ks + tg];
                af[mt][1] = As[r + 8][ks + tg];
                af[mt][2] = As[r][ks + tg + 4];
                af[mt][3] = As[r + 8][ks + tg + 4];
            }
#pragma unroll
            for (int nt = 0; nt < 4; ++nt) {
                int c = warpN + nt * 8 + g;
                bf[nt][0] = Bs[ks + tg][c];
                bf[nt][1] = Bs[ks + tg + 4][c];
            }
#pragma unroll
            for (int mt = 0; mt < 2; ++mt)
#pragma unroll
                for (int nt = 0; nt < 4; ++nt)
                    mma_tf32(acc[mt][nt], af[mt], bf[nt]);
        }
        __syncthreads();
    }
#pragma unroll
    for (int mt = 0; mt < 2; ++mt)
#pragma unroll
        for (int nt = 0; nt < 4; ++nt) {
            int r0 = bm + warpM + mt * 16 + g;
            int c0 = warpN + nt * 8 + 2 * tg;
            float2 v0 = {acc[mt][nt][0], acc[mt][nt][1]};
            float2 v1 = {acc[mt][nt][2], acc[mt][nt][3]};
            *(float2*)(O + (size_t)r0 * HDd + c0) = v0;
            *(float2*)(O + (size_t)(r0 + 8) * HDd + c0) = v1;
        }
}

// ---------------------------------------------------------------------------
// Head merge: g_A[b][s][d*16+h] = g_AH[b][h][s][d]
// ---------------------------------------------------------------------------
__global__ __launch_bounds__(256) void head_merge_kernel()
{
    int i = blockIdx.x * 256 + threadIdx.x;
    int j = i & 1023;
    int s = (i >> 10) & 2047;
    int b = i >> 21;
    int h = j & 15;
    int d = j >> 4;
    g_A[i] = g_AH[(size_t)((b*16 + h)*2048 + s) * 64 + d];
}

// ---------------------------------------------------------------------------
extern "C" void kernel_launch(void* const* d_in, const int* in_sizes, int n_in,
                              void* d_out, int out_size)
{
    const float* query = (const float*)d_in[0];
    const float* key   = (const float*)d_in[1];
    const float* value = (const float*)d_in[2];
    const float* Wq = (const float*)d_in[3];  const float* bq = (const float*)d_in[4];
    const float* Wk = (const float*)d_in[5];  const float* bk = (const float*)d_in[6];
    const float* Wv = (const float*)d_in[7];  const float* bv = (const float*)d_in[8];
    const float* Wo = (const float*)d_in[9];  const float* bo = (const float*)d_in[10];

    float* out   = (float*)d_out;
    float* probs = out + BSD;

    void* p;
    cudaGetSymbolAddress(&p, g_Q);  float* gQ  = (float*)p;
    cudaGetSymbolAddress(&p, g_K);  float* gK  = (float*)p;
    cudaGetSymbolAddress(&p, g_V);  float* gV  = (float*)p;
    cudaGetSymbolAddress(&p, g_Qh); float* gQh = (float*)p;
    cudaGetSymbolAddress(&p, g_Kh); float* gKh = (float*)p;
    cudaGetSymbolAddress(&p, g_Vh); float* gVh = (float*)p;
    cudaGetSymbolAddress(&p, g_A);  float* gA  = (float*)p;

    dim3 gemm_grid(Dd/128, MM/128);   // (8, 32)

    // 1) Projections (tf32 tensor cores)
    gemm_tf32_bias<<<gemm_grid, 256>>>(query, Wq, bq, gQ);
    gemm_tf32_bias<<<gemm_grid, 256>>>(key,   Wk, bk, gK);
    gemm_tf32_bias<<<gemm_grid, 256>>>(value, Wv, bv, gV);

    // 2) Head split into [b,h,s,d]
    head_split_kernel<<<BSD/256, 256>>>(gQ, gQh);
    head_split_kernel<<<BSD/256, 256>>>(gK, gKh);
    head_split_kernel<<<BSD/256, 256>>>(gV, gVh);

    // 3) Fused scores + head-softmax (big tiles): probs (d_out) + g_Sc planes
    fused_scores_softmax<<<dim3(Ss/32, Ss/64, Bb), 256>>>(probs);

    // 4) Attn * V per head (tf32)
    attnv_tf32<<<dim3(Ss/128, Bb*NHh), 256>>>();

    // 5) Merge heads
    head_merge_kernel<<<BSD/256, 256>>>();

    // 6) Output projection (tf32)
    gemm_tf32_bias<<<gemm_grid, 256>>>(gA, Wo, bo, out);
}

// round 11
// speedup vs baseline: 1.5124x; 1.4680x over previous
#include <cuda_runtime.h>
#include <math.h>
#include <stdint.h>

// Problem constants
#define Bb   2
#define Ss   2048
#define Dd   1024
#define NHh  16
#define HDd  64
#define MM   (Bb*Ss)
#define PLANE (Ss*Ss)
#define BSD  (Bb*Ss*Dd)

// ---------------- scratch (device globals) ----------------
__device__ float g_Wq[Dd*Dd];      // col-permuted Wq'
__device__ float g_Wk[Dd*Dd];
__device__ float g_Wv[Dd*Dd];
__device__ float g_Wo[Dd*Dd];      // row-permuted Wo'
__device__ float g_bp[3*Dd];       // permuted biases (q,k,v)
__device__ float g_Qh[BSD];        // [b,h,s,d]
__device__ float g_Kh[BSD];
__device__ float g_Vh[BSD];
__device__ float g_A[BSD];         // attn merged, interleaved [b,s,h*64+d]
__device__ float g_Sc[134217728];  // scores/probs scratch [b,h,l,n]

// ---------------------------------------------------------------------------
// tf32 helpers
// ---------------------------------------------------------------------------
__device__ __forceinline__ uint32_t f2tf(float f) {
    uint32_t u;
    asm("cvt.rna.tf32.f32 %0, %1;" : "=r"(u) : "f"(f));
    return u;
}

__device__ __forceinline__ void mma_tf32(float* c, const uint32_t* a, const uint32_t* b) {
    asm volatile(
        "mma.sync.aligned.m16n8k8.row.col.f32.tf32.tf32.f32 "
        "{%0,%1,%2,%3}, {%4,%5,%6,%7}, {%8,%9}, {%0,%1,%2,%3};\n"
        : "+f"(c[0]), "+f"(c[1]), "+f"(c[2]), "+f"(c[3])
        : "r"(a[0]), "r"(a[1]), "r"(a[2]), "r"(a[3]), "r"(b[0]), "r"(b[1]));
}

// ---------------------------------------------------------------------------
// Weight permutes.
// perm_w_cols: Wp[r][h*64+d] = W[r][d*16+h]  (column permutation, smem-staged)
// ---------------------------------------------------------------------------
__global__ __launch_bounds__(256) void perm_w_cols(
    const float* __restrict__ W, float* __restrict__ Wp)
{
    __shared__ float sm[8][1056];   // [r][h*66+d]
    const int row0 = blockIdx.x * 8;
    const int tid = threadIdx.x;
#pragma unroll
    for (int it = 0; it < 8; ++it) {
        int ch = it * 256 + tid;
        int r = ch >> 8, j4 = (ch & 255) << 2;
        float4 v = *(const float4*)(W + (size_t)(row0 + r) * Dd + j4);
        sm[r][((j4+0)&15)*66 + ((j4+0)>>4)] = v.x;
        sm[r][((j4+1)&15)*66 + ((j4+1)>>4)] = v.y;
        sm[r][((j4+2)&15)*66 + ((j4+2)>>4)] = v.z;
        sm[r][((j4+3)&15)*66 + ((j4+3)>>4)] = v.w;
    }
    __syncthreads();
#pragma unroll
    for (int it = 0; it < 8; ++it) {
        int ch = it * 256 + tid;
        int r = ch >> 8, j4 = (ch & 255) << 2;
        float4 o;
        o.x = sm[r][((j4+0)>>6)*66 + ((j4+0)&63)];
        o.y = sm[r][((j4+1)>>6)*66 + ((j4+1)&63)];
        o.z = sm[r][((j4+2)>>6)*66 + ((j4+2)&63)];
        o.w = sm[r][((j4+3)>>6)*66 + ((j4+3)&63)];
        *(float4*)(Wp + (size_t)(row0 + r) * Dd + j4) = o;
    }
}

// perm_wo_rows: Wp[h*64+d][:] = Wo[d*16+h][:]
__global__ __launch_bounds__(256) void perm_wo_rows(
    const float* __restrict__ Wo, float* __restrict__ Wp)
{
    int r = blockIdx.x;
    int src = ((r & 63) << 4) + (r >> 6);
    const float4* s4 = (const float4*)(Wo + (size_t)src * Dd);
    float4* d4 = (float4*)(Wp + (size_t)r * Dd);
    d4[threadIdx.x] = s4[threadIdx.x];
}

// perm_bias: bp[w*1024 + h*64+d] = b_w[d*16+h]
__global__ __launch_bounds__(256) void perm_bias(
    const float* __restrict__ b0, const float* __restrict__ b1,
    const float* __restrict__ b2, float* __restrict__ bp)
{
    int i = threadIdx.x + blockIdx.x * 256;   // 0..3071
    int w = i >> 10, j = i & 1023;
    const float* src = (w == 0) ? b0 : ((w == 1) ? b1 : b2);
    bp[i] = src[((j & 63) << 4) + (j >> 6)];
}

// ---------------------------------------------------------------------------
// Projection GEMM (tf32), reg-prefetch double-buffered, head-layout epilogue:
// out[b][h][s][d] = (A @ W')[m, h*64+d] + bp[h*64+d],  m = b*2048+s
// ---------------------------------------------------------------------------
__global__ __launch_bounds__(256) void gemm_tf32_headout(
    const float* __restrict__ A, const float* __restrict__ Wp,
    const float* __restrict__ bp, float* __restrict__ Oh)
{
    __shared__ uint32_t As_[128][36];
    __shared__ uint32_t Bs_[32][136];
    const int tid  = threadIdx.x;
    const int lane = tid & 31, w = tid >> 5;
    const int g = lane >> 2, tg = lane & 3;
    const int bm = blockIdx.y * 128, bn = blockIdx.x * 128;
    const int warpM = (w >> 2) * 64, warpN = (w & 3) * 32;

    float acc[4][4][4];
#pragma unroll
    for (int mt = 0; mt < 4; ++mt)
#pragma unroll
        for (int nt = 0; nt < 4; ++nt)
#pragma unroll
            for (int i = 0; i < 4; ++i) acc[mt][nt][i] = 0.f;

    float4 pa[4], pb[4];
    // preload k0 = 0
#pragma unroll
    for (int it = 0; it < 4; ++it) {
        int ch = tid + it * 256;
        int m = ch >> 3, kq = (ch & 7) << 2;
        pa[it] = *(const float4*)(A + (size_t)(bm + m) * Dd + kq);
        int kk = ch >> 5, n4 = (ch & 31) << 2;
        pb[it] = *(const float4*)(Wp + (size_t)kk * Dd + bn + n4);
    }
#pragma unroll
    for (int it = 0; it < 4; ++it) {
        int ch = tid + it * 256;
        int m = ch >> 3, kq = (ch & 7) << 2;
        uint4 ua = {f2tf(pa[it].x), f2tf(pa[it].y), f2tf(pa[it].z), f2tf(pa[it].w)};
        *(uint4*)&As_[m][kq] = ua;
        int kk = ch >> 5, n4 = (ch & 31) << 2;
        uint4 ub = {f2tf(pb[it].x), f2tf(pb[it].y), f2tf(pb[it].z), f2tf(pb[it].w)};
        *(uint4*)&Bs_[kk][n4] = ub;
    }
    __syncthreads();

    for (int k0 = 32; k0 <= Dd; k0 += 32) {
        if (k0 < Dd) {
#pragma unroll
            for (int it = 0; it < 4; ++it) {
                int ch = tid + it * 256;
                int m = ch >> 3, kq = (ch & 7) << 2;
                pa[it] = *(const float4*)(A + (size_t)(bm + m) * Dd + k0 + kq);
                int kk = ch >> 5, n4 = (ch & 31) << 2;
                pb[it] = *(const float4*)(Wp + (size_t)(k0 + kk) * Dd + bn + n4);
            }
        }
#pragma unroll
        for (int ks = 0; ks < 32; ks += 8) {
            uint32_t af[4][4], bf[4][2];
#pragma unroll
            for (int mt = 0; mt < 4; ++mt) {
                int r = warpM + mt * 16 + g;
                af[mt][0] = As_[r][ks + tg];
                af[mt][1] = As_[r + 8][ks + tg];
                af[mt][2] = As_[r][ks + tg + 4];
                af[mt][3] = As_[r + 8][ks + tg + 4];
            }
#pragma unroll
            for (int nt = 0; nt < 4; ++nt) {
                int c = warpN + nt * 8 + g;
                bf[nt][0] = Bs_[ks + tg][c];
                bf[nt][1] = Bs_[ks + tg + 4][c];
            }
#pragma unroll
            for (int mt = 0; mt < 4; ++mt)
#pragma unroll
                for (int nt = 0; nt < 4; ++nt)
                    mma_tf32(acc[mt][nt], af[mt], bf[nt]);
        }
        if (k0 < Dd) {
            __syncthreads();
#pragma unroll
            for (int it = 0; it < 4; ++it) {
                int ch = tid + it * 256;
                int m = ch >> 3, kq = (ch & 7) << 2;
                uint4 ua = {f2tf(pa[it].x), f2tf(pa[it].y), f2tf(pa[it].z), f2tf(pa[it].w)};
                *(uint4*)&As_[m][kq] = ua;
                int kk = ch >> 5, n4 = (ch & 31) << 2;
                uint4 ub = {f2tf(pb[it].x), f2tf(pb[it].y), f2tf(pb[it].z), f2tf(pb[it].w)};
                *(uint4*)&Bs_[kk][n4] = ub;
            }
            __syncthreads();
        }
    }

    // Head-layout epilogue: col c0 -> h = c0>>6, d = c0&63
#pragma unroll
    for (int mt = 0; mt < 4; ++mt)
#pragma unroll
        for (int nt = 0; nt < 4; ++nt) {
            int r0 = bm + warpM + mt * 16 + g;      // global m
            int c0 = bn + warpN + nt * 8 + 2 * tg;
            int b = r0 >> 11, s = r0 & 2047;
            int h = c0 >> 6, d = c0 & 63;
            float b0 = bp[c0], b1 = bp[c0 + 1];
            float* dst = Oh + ((size_t)(b * 16 + h) * 2048 + s) * 64 + d;
            float2 v0 = {acc[mt][nt][0] + b0, acc[mt][nt][1] + b1};
            float2 v1 = {acc[mt][nt][2] + b0, acc[mt][nt][3] + b1};
            *(float2*)(dst)          = v0;
            *(float2*)(dst + 8 * 64) = v1;           // row s+8, same b/h
        }
}

// ---------------------------------------------------------------------------
// Output projection GEMM (tf32), reg-prefetch, standard epilogue.
// C[M,1024] = A[M,1024] @ W'[1024,1024] + bias
// ---------------------------------------------------------------------------
__global__ __launch_bounds__(256) void gemm_tf32_bias(
    const float* __restrict__ A, const float* __restrict__ Wp,
    const float* __restrict__ bias, float* __restrict__ C)
{
    __shared__ uint32_t As_[128][36];
    __shared__ uint32_t Bs_[32][136];
    const int tid  = threadIdx.x;
    const int lane = tid & 31, w = tid >> 5;
    const int g = lane >> 2, tg = lane & 3;
    const int bm = blockIdx.y * 128, bn = blockIdx.x * 128;
    const int warpM = (w >> 2) * 64, warpN = (w & 3) * 32;

    float acc[4][4][4];
#pragma unroll
    for (int mt = 0; mt < 4; ++mt)
#pragma unroll
        for (int nt = 0; nt < 4; ++nt)
#pragma unroll
            for (int i = 0; i < 4; ++i) acc[mt][nt][i] = 0.f;

    float4 pa[4], pb[4];
#pragma unroll
    for (int it = 0; it < 4; ++it) {
        int ch = tid + it * 256;
        int m = ch >> 3, kq = (ch & 7) << 2;
        pa[it] = *(const float4*)(A + (size_t)(bm + m) * Dd + kq);
        int kk = ch >> 5, n4 = (ch & 31) << 2;
        pb[it] = *(const float4*)(Wp + (size_t)kk * Dd + bn + n4);
    }
#pragma unroll
    for (int it = 0; it < 4; ++it) {
        int ch = tid + it * 256;
        int m = ch >> 3, kq = (ch & 7) << 2;
        uint4 ua = {f2tf(pa[it].x), f2tf(pa[it].y), f2tf(pa[it].z), f2tf(pa[it].w)};
        *(uint4*)&As_[m][kq] = ua;
        int kk = ch >> 5, n4 = (ch & 31) << 2;
        uint4 ub = {f2tf(pb[it].x), f2tf(pb[it].y), f2tf(pb[it].z), f2tf(pb[it].w)};
        *(uint4*)&Bs_[kk][n4] = ub;
    }
    __syncthreads();

    for (int k0 = 32; k0 <= Dd; k0 += 32) {
        if (k0 < Dd) {
#pragma unroll
            for (int it = 0; it < 4; ++it) {
                int ch = tid + it * 256;
                int m = ch >> 3, kq = (ch & 7) << 2;
                pa[it] = *(const float4*)(A + (size_t)(bm + m) * Dd + k0 + kq);
                int kk = ch >> 5, n4 = (ch & 31) << 2;
                pb[it] = *(const float4*)(Wp + (size_t)(k0 + kk) * Dd + bn + n4);
            }
        }
#pragma unroll
        for (int ks = 0; ks < 32; ks += 8) {
            uint32_t af[4][4], bf[4][2];
#pragma unroll
            for (int mt = 0; mt < 4; ++mt) {
                int r = warpM + mt * 16 + g;
                af[mt][0] = As_[r][ks + tg];
                af[mt][1] = As_[r + 8][ks + tg];
                af[mt][2] = As_[r][ks + tg + 4];
                af[mt][3] = As_[r + 8][ks + tg + 4];
            }
#pragma unroll
            for (int nt = 0; nt < 4; ++nt) {
                int c = warpN + nt * 8 + g;
                bf[nt][0] = Bs_[ks + tg][c];
                bf[nt][1] = Bs_[ks + tg + 4][c];
            }
#pragma unroll
            for (int mt = 0; mt < 4; ++mt)
#pragma unroll
                for (int nt = 0; nt < 4; ++nt)
                    mma_tf32(acc[mt][nt], af[mt], bf[nt]);
        }
        if (k0 < Dd) {
            __syncthreads();
#pragma unroll
            for (int it = 0; it < 4; ++it) {
                int ch = tid + it * 256;
                int m = ch >> 3, kq = (ch & 7) << 2;
                uint4 ua = {f2tf(pa[it].x), f2tf(pa[it].y), f2tf(pa[it].z), f2tf(pa[it].w)};
                *(uint4*)&As_[m][kq] = ua;
                int kk = ch >> 5, n4 = (ch & 31) << 2;
                uint4 ub = {f2tf(pb[it].x), f2tf(pb[it].y), f2tf(pb[it].z), f2tf(pb[it].w)};
                *(uint4*)&Bs_[kk][n4] = ub;
            }
            __syncthreads();
        }
    }
#pragma unroll
    for (int mt = 0; mt < 4; ++mt)
#pragma unroll
        for (int nt = 0; nt < 4; ++nt) {
            int r0 = bm + warpM + mt * 16 + g;
            int c0 = bn + warpN + nt * 8 + 2 * tg;
            float b0 = bias[c0], b1 = bias[c0 + 1];
            float2 v0 = {acc[mt][nt][0] + b0, acc[mt][nt][1] + b1};
            float2 v1 = {acc[mt][nt][2] + b0, acc[mt][nt][3] + b1};
            *(float2*)(C + (size_t)r0 * Dd + c0) = v0;
            *(float2*)(C + (size_t)(r0 + 8) * Dd + c0) = v1;
        }
}

// ---------------------------------------------------------------------------
// Scores (tf32 NT): per plane z: Sc[l,n] = 0.125 * Qh[l,:] . Kh[n,:], K=64
// ---------------------------------------------------------------------------
__global__ __launch_bounds__(256) void scores_tf32()
{
    __shared__ uint32_t As_[128][36];
    __shared__ uint32_t Bs_[32][136];
    const int tid  = threadIdx.x;
    const int lane = tid & 31, w = tid >> 5;
    const int g = lane >> 2, tg = lane & 3;
    const int z  = blockIdx.z;
    const int bm = blockIdx.y * 128, bn = blockIdx.x * 128;
    const int warpM = (w >> 2) * 64, warpN = (w & 3) * 32;
    const float* Q  = g_Qh + (size_t)z * (Ss*HDd);
    const float* Kh = g_Kh + (size_t)z * (Ss*HDd);

    float acc[4][4][4];
#pragma unroll
    for (int mt = 0; mt < 4; ++mt)
#pragma unroll
        for (int nt = 0; nt < 4; ++nt)
#pragma unroll
            for (int i = 0; i < 4; ++i) acc[mt][nt][i] = 0.f;

    for (int k0 = 0; k0 < HDd; k0 += 32) {
#pragma unroll
        for (int it = 0; it < 4; ++it) {
            int ch = tid + it * 256;
            int m = ch >> 3, kq = (ch & 7) << 2;
            float4 v = *(const float4*)(Q + (size_t)(bm + m) * HDd + k0 + kq);
            uint4 u = {f2tf(v.x), f2tf(v.y), f2tf(v.z), f2tf(v.w)};
            *(uint4*)&As_[m][kq] = u;
        }
#pragma unroll
        for (int it = 0; it < 4; ++it) {
            int ch = tid + it * 256;
            int n = ch >> 3, kq = (ch & 7) << 2;
            float4 v = *(const float4*)(Kh + (size_t)(bn + n) * HDd + k0 + kq);
            Bs_[kq + 0][n] = f2tf(v.x);
            Bs_[kq + 1][n] = f2tf(v.y);
            Bs_[kq + 2][n] = f2tf(v.z);
            Bs_[kq + 3][n] = f2tf(v.w);
        }
        __syncthreads();
#pragma unroll
        for (int ks = 0; ks < 32; ks += 8) {
            uint32_t af[4][4], bf[4][2];
#pragma unroll
            for (int mt = 0; mt < 4; ++mt) {
                int r = warpM + mt * 16 + g;
                af[mt][0] = As_[r][ks + tg];
                af[mt][1] = As_[r + 8][ks + tg];
                af[mt][2] = As_[r][ks + tg + 4];
                af[mt][3] = As_[r + 8][ks + tg + 4];
            }
#pragma unroll
            for (int nt = 0; nt < 4; ++nt) {
                int c = warpN + nt * 8 + g;
                bf[nt][0] = Bs_[ks + tg][c];
                bf[nt][1] = Bs_[ks + tg + 4][c];
            }
#pragma unroll
            for (int mt = 0; mt < 4; ++mt)
#pragma unroll
                for (int nt = 0; nt < 4; ++nt)
                    mma_tf32(acc[mt][nt], af[mt], bf[nt]);
        }
        __syncthreads();
    }
    float* out = g_Sc + (size_t)z * PLANE;
#pragma unroll
    for (int mt = 0; mt < 4; ++mt)
#pragma unroll
        for (int nt = 0; nt < 4; ++nt) {
            int r0 = bm + warpM + mt * 16 + g;
            int c0 = bn + warpN + nt * 8 + 2 * tg;
            float2 v0 = {0.125f*acc[mt][nt][0], 0.125f*acc[mt][nt][1]};
            float2 v1 = {0.125f*acc[mt][nt][2], 0.125f*acc[mt][nt][3]};
            *(float2*)(out + (size_t)r0 * Ss + c0) = v0;
            *(float2*)(out + (size_t)(r0 + 8) * Ss + c0) = v1;
        }
}

// ---------------------------------------------------------------------------
// Softmax over HEAD axis, one thread per (b,l,n).
// ---------------------------------------------------------------------------
__global__ __launch_bounds__(256) void softmax_kernel(float* __restrict__ probs)
{
    int i = blockIdx.x * 256 + threadIdx.x;
    int n = i & 2047;
    int l = (i >> 11) & 2047;
    int b = i >> 22;
    size_t off = (size_t)l * Ss + n;

    float s[16];
#pragma unroll
    for (int h = 0; h < 16; ++h)
        s[h] = g_Sc[(size_t)(b*16 + h) * PLANE + off];

    float m = s[0];
#pragma unroll
    for (int h = 1; h < 16; ++h) m = fmaxf(m, s[h]);
    float sum = 0.f;
#pragma unroll
    for (int h = 0; h < 16; ++h) { s[h] = __expf(s[h] - m); sum += s[h]; }
    float r = 1.0f / sum;

    float* po = probs + (size_t)i * 16;
#pragma unroll
    for (int h4 = 0; h4 < 16; h4 += 4) {
        float4 o = {s[h4]*r, s[h4+1]*r, s[h4+2]*r, s[h4+3]*r};
        *(float4*)(po + h4) = o;
    }
#pragma unroll
    for (int h = 0; h < 16; ++h)
        g_Sc[(size_t)(b*16 + h) * PLANE + off] = s[h] * r;
}

// ---------------------------------------------------------------------------
// Attn*V (tf32), reg-prefetch; writes directly into interleaved activation
// layout g_A[b][s][h*64+d]  (merge kernel eliminated).
// ---------------------------------------------------------------------------
__global__ __launch_bounds__(256) void attnv_tf32()
{
    __shared__ uint32_t As_[128][36];
    __shared__ uint32_t Bs_[32][72];
    const int tid  = threadIdx.x;
    const int lane = tid & 31, w = tid >> 5;
    const int g = lane >> 2, tg = lane & 3;
    const int z  = blockIdx.y;
    const int bm = blockIdx.x * 128;
    const int warpM = (w >> 1) * 32, warpN = (w & 1) * 32;
    const float* P = g_Sc + (size_t)z * PLANE;
    const float* V = g_Vh + (size_t)z * (Ss*HDd);
    const int bz = z >> 4, hz = z & 15;
    float* O = g_A + ((size_t)bz * 2048) * 1024 + hz * 64;

    float acc[2][4][4];
#pragma unroll
    for (int mt = 0; mt < 2; ++mt)
#pragma unroll
        for (int nt = 0; nt < 4; ++nt)
#pragma unroll
            for (int i = 0; i < 4; ++i) acc[mt][nt][i] = 0.f;

    float4 pa[4], pb[2];
    // preload k0 = 0
#pragma unroll
    for (int it = 0; it < 4; ++it) {
        int ch = tid + it * 256;
        int m = ch >> 3, kq = (ch & 7) << 2;
        pa[it] = *(const float4*)(P + (size_t)(bm + m) * Ss + kq);
    }
#pragma unroll
    for (int it = 0; it < 2; ++it) {
        int ch = tid + it * 256;
        int kk = ch >> 4, n4 = (ch & 15) << 2;
        pb[it] = *(const float4*)(V + (size_t)kk * HDd + n4);
    }
#pragma unroll
    for (int it = 0; it < 4; ++it) {
        int ch = tid + it * 256;
        int m = ch >> 3, kq = (ch & 7) << 2;
        uint4 u = {f2tf(pa[it].x), f2tf(pa[it].y), f2tf(pa[it].z), f2tf(pa[it].w)};
        *(uint4*)&As_[m][kq] = u;
    }
#pragma unroll
    for (int it = 0; it < 2; ++it) {
        int ch = tid + it * 256;
        int kk = ch >> 4, n4 = (ch & 15) << 2;
        uint4 u = {f2tf(pb[it].x), f2tf(pb[it].y), f2tf(pb[it].z), f2tf(pb[it].w)};
        *(uint4*)&Bs_[kk][n4] = u;
    }
    __syncthreads();

    for (int k0 = 32; k0 <= Ss; k0 += 32) {
        if (k0 < Ss) {
#pragma unroll
            for (int it = 0; it < 4; ++it) {
                int ch = tid + it * 256;
                int m = ch >> 3, kq = (ch & 7) << 2;
                pa[it] = *(const float4*)(P + (size_t)(bm + m) * Ss + k0 + kq);
            }
#pragma unroll
            for (int it = 0; it < 2; ++it) {
                int ch = tid + it * 256;
                int kk = ch >> 4, n4 = (ch & 15) << 2;
                pb[it] = *(const float4*)(V + (size_t)(k0 + kk) * HDd + n4);
            }
        }
#pragma unroll
        for (int ks = 0; ks < 32; ks += 8) {
            uint32_t af[2][4], bf[4][2];
#pragma unroll
            for (int mt = 0; mt < 2; ++mt) {
                int r = warpM + mt * 16 + g;
                af[mt][0] = As_[r][ks + tg];
                af[mt][1] = As_[r + 8][ks + tg];
                af[mt][2] = As_[r][ks + tg + 4];
                af[mt][3] = As_[r + 8][ks + tg + 4];
            }
#pragma unroll
            for (int nt = 0; nt < 4; ++nt) {
                int c = warpN + nt * 8 + g;
                bf[nt][0] = Bs_[ks + tg][c];
                bf[nt][1] = Bs_[ks + tg + 4][c];
            }
#pragma unroll
            for (int mt = 0; mt < 2; ++mt)
#pragma unroll
                for (int nt = 0; nt < 4; ++nt)
                    mma_tf32(acc[mt][nt], af[mt], bf[nt]);
        }
        if (k0 < Ss) {
            __syncthreads();
#pragma unroll
            for (int it = 0; it < 4; ++it) {
                int ch = tid + it * 256;
                int m = ch >> 3, kq = (ch & 7) << 2;
                uint4 u = {f2tf(pa[it].x), f2tf(pa[it].y), f2tf(pa[it].z), f2tf(pa[it].w)};
                *(uint4*)&As_[m][kq] = u;
            }
#pragma unroll
            for (int it = 0; it < 2; ++it) {
                int ch = tid + it * 256;
                int kk = ch >> 4, n4 = (ch & 15) << 2;
                uint4 u = {f2tf(pb[it].x), f2tf(pb[it].y), f2tf(pb[it].z), f2tf(pb[it].w)};
                *(uint4*)&Bs_[kk][n4] = u;
            }
            __syncthreads();
        }
    }
#pragma unroll
    for (int mt = 0; mt < 2; ++mt)
#pragma unroll
        for (int nt = 0; nt < 4; ++nt) {
            int r0 = bm + warpM + mt * 16 + g;      // s
            int c0 = warpN + nt * 8 + 2 * tg;       // d
            float2 v0 = {acc[mt][nt][0], acc[mt][nt][1]};
            float2 v1 = {acc[mt][nt][2], acc[mt][nt][3]};
            *(float2*)(O + (size_t)r0 * 1024 + c0) = v0;
            *(float2*)(O + (size_t)(r0 + 8) * 1024 + c0) = v1;
        }
}

// ---------------------------------------------------------------------------
extern "C" void kernel_launch(void* const* d_in, const int* in_sizes, int n_in,
                              void* d_out, int out_size)
{
    const float* query = (const float*)d_in[0];
    const float* key   = (const float*)d_in[1];
    const float* value = (const float*)d_in[2];
    const float* Wq = (const float*)d_in[3];  const float* bq = (const float*)d_in[4];
    const float* Wk = (const float*)d_in[5];  const float* bk = (const float*)d_in[6];
    const float* Wv = (const float*)d_in[7];  const float* bv = (const float*)d_in[8];
    const float* Wo = (const float*)d_in[9];  const float* bo = (const float*)d_in[10];

    float* out   = (float*)d_out;
    float* probs = out + BSD;

    void* p;
    cudaGetSymbolAddress(&p, g_Wq); float* gWq = (float*)p;
    cudaGetSymbolAddress(&p, g_Wk); float* gWk = (float*)p;
    cudaGetSymbolAddress(&p, g_Wv); float* gWv = (float*)p;
    cudaGetSymbolAddress(&p, g_Wo); float* gWo = (float*)p;
    cudaGetSymbolAddress(&p, g_bp); float* gbp = (float*)p;
    cudaGetSymbolAddress(&p, g_Qh); float* gQh = (float*)p;
    cudaGetSymbolAddress(&p, g_Kh); float* gKh = (float*)p;
    cudaGetSymbolAddress(&p, g_Vh); float* gVh = (float*)p;
    cudaGetSymbolAddress(&p, g_A);  float* gA  = (float*)p;

    dim3 gemm_grid(Dd/128, MM/128);   // (8, 32)

    // 0) Weight/bias permutations
    perm_w_cols<<<128, 256>>>(Wq, gWq);
    perm_w_cols<<<128, 256>>>(Wk, gWk);
    perm_w_cols<<<128, 256>>>(Wv, gWv);
    perm_wo_rows<<<1024, 256>>>(Wo, gWo);
    perm_bias<<<12, 256>>>(bq, bk, bv, gbp);

    // 1) Projections -> head layout directly (head_split eliminated)
    gemm_tf32_headout<<<gemm_grid, 256>>>(query, gWq, gbp,        gQh);
    gemm_tf32_headout<<<gemm_grid, 256>>>(key,   gWk, gbp + 1024, gKh);
    gemm_tf32_headout<<<gemm_grid, 256>>>(value, gWv, gbp + 2048, gVh);

    // 2) Per-head scores into g_Sc
    scores_tf32<<<dim3(Ss/128, Ss/128, Bb*NHh), 256>>>();

    // 3) Softmax over heads: probs output + normalized g_Sc
    softmax_kernel<<<(Bb*(size_t)Ss*Ss)/256, 256>>>(probs);

    // 4) Attn*V -> interleaved activation layout (merge eliminated)
    attnv_tf32<<<dim3(Ss/128, Bb*NHh), 256>>>();

    // 5) Output projection with row-permuted Wo
    gemm_tf32_bias<<<gemm_grid, 256>>>(gA, gWo, bo, out);
}

// round 12
// speedup vs baseline: 1.9884x; 1.3147x over previous
#include <cuda_runtime.h>
#include <cuda_fp16.h>
#include <math.h>
#include <stdint.h>

// Problem constants
#define Bb   2
#define Ss   2048
#define Dd   1024
#define NHh  16
#define HDd  64
#define MM   (Bb*Ss)
#define PLANE (Ss*Ss)
#define BSD  (Bb*Ss*Dd)

// ---------------- scratch (device globals) ----------------
__device__ __half g_Wq[Dd*Dd];     // permuted+transposed: [n'][k] fp16
__device__ __half g_Wk[Dd*Dd];
__device__ __half g_Wv[Dd*Dd];
__device__ __half g_Wo[Dd*Dd];     // row-permuted+transposed: [n][k'] fp16
__device__ float  g_bp[3*Dd];      // permuted biases (q,k,v)
__device__ __half g_Qh[BSD];       // [b,h,s,d] fp16
__device__ __half g_Kh[BSD];
__device__ __half g_Vh[BSD];
__device__ __half g_A[BSD];        // merged activations [b,s,h*64+d] fp16
__device__ float  g_Sc[134217728]; // raw scaled scores [b,h,l,n] fp32
__device__ __half g_P[134217728];  // normalized probs  [b,h,l,n] fp16

// ---------------------------------------------------------------------------
// helpers
// ---------------------------------------------------------------------------
__device__ __forceinline__ void mma_f16(float* c, const uint32_t* a, const uint32_t* b) {
    asm volatile(
        "mma.sync.aligned.m16n8k16.row.col.f32.f16.f16.f32 "
        "{%0,%1,%2,%3}, {%4,%5,%6,%7}, {%8,%9}, {%0,%1,%2,%3};\n"
        : "+f"(c[0]), "+f"(c[1]), "+f"(c[2]), "+f"(c[3])
        : "r"(a[0]), "r"(a[1]), "r"(a[2]), "r"(a[3]), "r"(b[0]), "r"(b[1]));
}

union H8 { __half h[8]; uint4 u; };
union H16 { __half h[16]; uint4 u[2]; };

// ---------------------------------------------------------------------------
// perm_wT: Wt[h*64+d][r] = (half) W[r][d*16+h]   (for Wq/Wk/Wv)
// Block = 16 source rows. smem 16x1040 halves (33KB).
// ---------------------------------------------------------------------------
__global__ __launch_bounds__(256) void perm_wT(
    const float* __restrict__ W, __half* __restrict__ Wt)
{
    __shared__ __half sm[16][1040];
    const int r0 = blockIdx.x * 16;
    const int tid = threadIdx.x;
#pragma unroll
    for (int it = 0; it < 16; ++it) {
        int ch = it * 256 + tid;
        int r = ch >> 8, c4 = (ch & 255) << 2;
        float4 v = *(const float4*)(W + (size_t)(r0 + r) * Dd + c4);
        __half2 p0 = __floats2half2_rn(v.x, v.y);
        __half2 p1 = __floats2half2_rn(v.z, v.w);
        *(__half2*)&sm[r][c4]     = p0;
        *(__half2*)&sm[r][c4 + 2] = p1;
    }
    __syncthreads();
#pragma unroll
    for (int i = 0; i < 4; ++i) {
        int cp = tid + i * 256;                       // output row (n')
        int src = ((cp & 63) << 4) + (cp >> 6);       // source col
        H16 t;
#pragma unroll
        for (int r = 0; r < 16; ++r) t.h[r] = sm[r][src];
        uint4* dst = (uint4*)(Wt + (size_t)cp * Dd + r0);
        dst[0] = t.u[0];
        dst[1] = t.u[1];
    }
}

// ---------------------------------------------------------------------------
// perm_woT: Wt[c][j] = (half) Wo[(j&63)*16 + (j>>6)][c]
// Block = 16 output rows (c). smem 1024x20 halves (40KB).
// ---------------------------------------------------------------------------
__global__ __launch_bounds__(256) void perm_woT(
    const float* __restrict__ Wo, __half* __restrict__ Wt)
{
    __shared__ __half sm[1024][20];
    const int c0 = blockIdx.x * 16;
    const int tid = threadIdx.x;
#pragma unroll
    for (int it = 0; it < 16; ++it) {
        int ch = it * 256 + tid;
        int r = ch >> 2, c4 = (ch & 3) << 2;
        float4 v = *(const float4*)(Wo + (size_t)r * Dd + c0 + c4);
        __half2 p0 = __floats2half2_rn(v.x, v.y);
        __half2 p1 = __floats2half2_rn(v.z, v.w);
        *(__half2*)&sm[r][c4]     = p0;
        *(__half2*)&sm[r][c4 + 2] = p1;
    }
    __syncthreads();
    const int lc = tid >> 4;        // 0..15
    const int jc = tid & 15;
#pragma unroll
    for (int it = 0; it < 8; ++it) {
        int j0 = jc * 8 + it * 128;
        H8 t;
#pragma unroll
        for (int i = 0; i < 8; ++i) {
            int j = j0 + i;
            int src = ((j & 63) << 4) + (j >> 6);
            t.h[i] = sm[src][lc];
        }
        *(uint4*)(Wt + (size_t)(c0 + lc) * Dd + j0) = t.u;
    }
}

// perm_bias: bp[w*1024 + h*64+d] = b_w[d*16+h]
__global__ __launch_bounds__(256) void perm_bias(
    const float* __restrict__ b0, const float* __restrict__ b1,
    const float* __restrict__ b2, float* __restrict__ bp)
{
    int i = threadIdx.x + blockIdx.x * 256;
    int w = i >> 10, j = i & 1023;
    const float* src = (w == 0) ? b0 : ((w == 1) ? b1 : b2);
    bp[i] = src[((j & 63) << 4) + (j >> 6)];
}

// ---------------------------------------------------------------------------
// Projection GEMM (f16 mma, fp32 in): Oh[b,h,s,d] = (x @ W')[m, h*64+d] + bp
// Block 128x128, BK=32, 256 thr, 8 warps (2m x 4n), warp 64x32. Reg prefetch.
// ---------------------------------------------------------------------------
__global__ __launch_bounds__(256) void gemm_f16_headout(
    const float* __restrict__ A, const __half* __restrict__ Wt,
    const float* __restrict__ bp, __half* __restrict__ Oh)
{
    __shared__ __half As_[128][40];   // [m][k] pad40 halves (80B rows)
    __shared__ __half Bs_[128][40];   // [n][k]
    const int tid  = threadIdx.x;
    const int lane = tid & 31, w = tid >> 5;
    const int g = lane >> 2, tg = lane & 3;
    const int bm = blockIdx.y * 128, bn = blockIdx.x * 128;
    const int warpM = (w >> 2) * 64, warpN = (w & 3) * 32;

    float acc[4][4][4];
#pragma unroll
    for (int mt = 0; mt < 4; ++mt)
#pragma unroll
        for (int nt = 0; nt < 4; ++nt)
#pragma unroll
            for (int i = 0; i < 4; ++i) acc[mt][nt][i] = 0.f;

    float4 pa[4]; uint4 pw[2];
#pragma unroll
    for (int it = 0; it < 4; ++it) {
        int ch = tid + it * 256;
        int m = ch >> 3, kq = (ch & 7) << 2;
        pa[it] = *(const float4*)(A + (size_t)(bm + m) * Dd + kq);
    }
#pragma unroll
    for (int it = 0; it < 2; ++it) {
        int ch = tid + it * 256;
        int n = ch >> 2, kc = (ch & 3) << 3;
        pw[it] = *(const uint4*)(Wt + (size_t)(bn + n) * Dd + kc);
    }
#pragma unroll
    for (int it = 0; it < 4; ++it) {
        int ch = tid + it * 256;
        int m = ch >> 3, kq = (ch & 7) << 2;
        *(__half2*)&As_[m][kq]     = __floats2half2_rn(pa[it].x, pa[it].y);
        *(__half2*)&As_[m][kq + 2] = __floats2half2_rn(pa[it].z, pa[it].w);
    }
#pragma unroll
    for (int it = 0; it < 2; ++it) {
        int ch = tid + it * 256;
        int n = ch >> 2, kc = (ch & 3) << 3;
        *(uint4*)&Bs_[n][kc] = pw[it];
    }
    __syncthreads();

    for (int k0 = 32; k0 <= Dd; k0 += 32) {
        if (k0 < Dd) {
#pragma unroll
            for (int it = 0; it < 4; ++it) {
                int ch = tid + it * 256;
                int m = ch >> 3, kq = (ch & 7) << 2;
                pa[it] = *(const float4*)(A + (size_t)(bm + m) * Dd + k0 + kq);
            }
#pragma unroll
            for (int it = 0; it < 2; ++it) {
                int ch = tid + it * 256;
                int n = ch >> 2, kc = (ch & 3) << 3;
                pw[it] = *(const uint4*)(Wt + (size_t)(bn + n) * Dd + k0 + kc);
            }
        }
#pragma unroll
        for (int ks = 0; ks < 32; ks += 16) {
            uint32_t af[4][4], bf[4][2];
#pragma unroll
            for (int mt = 0; mt < 4; ++mt) {
                int r = warpM + mt * 16 + g;
                af[mt][0] = *(uint32_t*)&As_[r][ks + 2*tg];
                af[mt][1] = *(uint32_t*)&As_[r + 8][ks + 2*tg];
                af[mt][2] = *(uint32_t*)&As_[r][ks + 2*tg + 8];
                af[mt][3] = *(uint32_t*)&As_[r + 8][ks + 2*tg + 8];
            }
#pragma unroll
            for (int nt = 0; nt < 4; ++nt) {
                int c = warpN + nt * 8 + g;
                bf[nt][0] = *(uint32_t*)&Bs_[c][ks + 2*tg];
                bf[nt][1] = *(uint32_t*)&Bs_[c][ks + 2*tg + 8];
            }
#pragma unroll
            for (int mt = 0; mt < 4; ++mt)
#pragma unroll
                for (int nt = 0; nt < 4; ++nt)
                    mma_f16(acc[mt][nt], af[mt], bf[nt]);
        }
        if (k0 < Dd) {
            __syncthreads();
#pragma unroll
            for (int it = 0; it < 4; ++it) {
                int ch = tid + it * 256;
                int m = ch >> 3, kq = (ch & 7) << 2;
                *(__half2*)&As_[m][kq]     = __floats2half2_rn(pa[it].x, pa[it].y);
                *(__half2*)&As_[m][kq + 2] = __floats2half2_rn(pa[it].z, pa[it].w);
            }
#pragma unroll
            for (int it = 0; it < 2; ++it) {
                int ch = tid + it * 256;
                int n = ch >> 2, kc = (ch & 3) << 3;
                *(uint4*)&Bs_[n][kc] = pw[it];
            }
            __syncthreads();
        }
    }

#pragma unroll
    for (int mt = 0; mt < 4; ++mt)
#pragma unroll
        for (int nt = 0; nt < 4; ++nt) {
            int r0 = bm + warpM + mt * 16 + g;
            int c0 = bn + warpN + nt * 8 + 2 * tg;
            int b = r0 >> 11, s = r0 & 2047;
            int h = c0 >> 6, d = c0 & 63;
            float b0 = bp[c0], b1 = bp[c0 + 1];
            __half* dst = Oh + ((size_t)(b * 16 + h) * 2048 + s) * 64 + d;
            *(__half2*)(dst)          = __floats2half2_rn(acc[mt][nt][0] + b0, acc[mt][nt][1] + b1);
            *(__half2*)(dst + 8 * 64) = __floats2half2_rn(acc[mt][nt][2] + b0, acc[mt][nt][3] + b1);
        }
}

// ---------------------------------------------------------------------------
// Output projection (f16 x f16 -> fp32): out = g_A @ Wo' + bo
// ---------------------------------------------------------------------------
__global__ __launch_bounds__(256) void gemm_f16_bias(
    const __half* __restrict__ A, const __half* __restrict__ Wt,
    const float* __restrict__ bias, float* __restrict__ C)
{
    __shared__ __half As_[128][40];
    __shared__ __half Bs_[128][40];
    const int tid  = threadIdx.x;
    const int lane = tid & 31, w = tid >> 5;
    const int g = lane >> 2, tg = lane & 3;
    const int bm = blockIdx.y * 128, bn = blockIdx.x * 128;
    const int warpM = (w >> 2) * 64, warpN = (w & 3) * 32;

    float acc[4][4][4];
#pragma unroll
    for (int mt = 0; mt < 4; ++mt)
#pragma unroll
        for (int nt = 0; nt < 4; ++nt)
#pragma unroll
            for (int i = 0; i < 4; ++i) acc[mt][nt][i] = 0.f;

    uint4 pa[2], pw[2];
#pragma unroll
    for (int it = 0; it < 2; ++it) {
        int ch = tid + it * 256;
        int m = ch >> 2, kc = (ch & 3) << 3;
        pa[it] = *(const uint4*)(A + (size_t)(bm + m) * Dd + kc);
        pw[it] = *(const uint4*)(Wt + (size_t)(bn + m) * Dd + kc);
    }
#pragma unroll
    for (int it = 0; it < 2; ++it) {
        int ch = tid + it * 256;
        int m = ch >> 2, kc = (ch & 3) << 3;
        *(uint4*)&As_[m][kc] = pa[it];
        *(uint4*)&Bs_[m][kc] = pw[it];
    }
    __syncthreads();

    for (int k0 = 32; k0 <= Dd; k0 += 32) {
        if (k0 < Dd) {
#pragma unroll
            for (int it = 0; it < 2; ++it) {
                int ch = tid + it * 256;
                int m = ch >> 2, kc = (ch & 3) << 3;
                pa[it] = *(const uint4*)(A + (size_t)(bm + m) * Dd + k0 + kc);
                pw[it] = *(const uint4*)(Wt + (size_t)(bn + m) * Dd + k0 + kc);
            }
        }
#pragma unroll
        for (int ks = 0; ks < 32; ks += 16) {
            uint32_t af[4][4], bf[4][2];
#pragma unroll
            for (int mt = 0; mt < 4; ++mt) {
                int r = warpM + mt * 16 + g;
                af[mt][0] = *(uint32_t*)&As_[r][ks + 2*tg];
                af[mt][1] = *(uint32_t*)&As_[r + 8][ks + 2*tg];
                af[mt][2] = *(uint32_t*)&As_[r][ks + 2*tg + 8];
                af[mt][3] = *(uint32_t*)&As_[r + 8][ks + 2*tg + 8];
            }
#pragma unroll
            for (int nt = 0; nt < 4; ++nt) {
                int c = warpN + nt * 8 + g;
                bf[nt][0] = *(uint32_t*)&Bs_[c][ks + 2*tg];
                bf[nt][1] = *(uint32_t*)&Bs_[c][ks + 2*tg + 8];
            }
#pragma unroll
            for (int mt = 0; mt < 4; ++mt)
#pragma unroll
                for (int nt = 0; nt < 4; ++nt)
                    mma_f16(acc[mt][nt], af[mt], bf[nt]);
        }
        if (k0 < Dd) {
            __syncthreads();
#pragma unroll
            for (int it = 0; it < 2; ++it) {
                int ch = tid + it * 256;
                int m = ch >> 2, kc = (ch & 3) << 3;
                *(uint4*)&As_[m][kc] = pa[it];
                *(uint4*)&Bs_[m][kc] = pw[it];
            }
            __syncthreads();
        }
    }
#pragma unroll
    for (int mt = 0; mt < 4; ++mt)
#pragma unroll
        for (int nt = 0; nt < 4; ++nt) {
            int r0 = bm + warpM + mt * 16 + g;
            int c0 = bn + warpN + nt * 8 + 2 * tg;
            float b0 = bias[c0], b1 = bias[c0 + 1];
            float2 v0 = {acc[mt][nt][0] + b0, acc[mt][nt][1] + b1};
            float2 v1 = {acc[mt][nt][2] + b0, acc[mt][nt][3] + b1};
            *(float2*)(C + (size_t)r0 * Dd + c0) = v0;
            *(float2*)(C + (size_t)(r0 + 8) * Dd + c0) = v1;
        }
}

// ---------------------------------------------------------------------------
// Scores (f16): per plane z: Sc[l,n] = 0.125 * Qh[l,:].Kh[n,:], K=64 one-shot.
// Block 128x128, 8 warps (2m x 4n), warp 64x32.
// ---------------------------------------------------------------------------
__global__ __launch_bounds__(256) void scores_f16()
{
    __shared__ __half Qs_[128][72];   // pad72 halves = 144B rows
    __shared__ __half Ks_[128][72];
    const int tid  = threadIdx.x;
    const int lane = tid & 31, w = tid >> 5;
    const int g = lane >> 2, tg = lane & 3;
    const int z  = blockIdx.z;
    const int bm = blockIdx.y * 128, bn = blockIdx.x * 128;
    const int warpM = (w >> 2) * 64, warpN = (w & 3) * 32;
    const __half* Q  = g_Qh + (size_t)z * (Ss*HDd);
    const __half* Kp = g_Kh + (size_t)z * (Ss*HDd);

    float acc[4][4][4];
#pragma unroll
    for (int mt = 0; mt < 4; ++mt)
#pragma unroll
        for (int nt = 0; nt < 4; ++nt)
#pragma unroll
            for (int i = 0; i < 4; ++i) acc[mt][nt][i] = 0.f;

#pragma unroll
    for (int it = 0; it < 4; ++it) {
        int ch = tid + it * 256;
        int s = ch >> 3, dc = (ch & 7) << 3;
        *(uint4*)&Qs_[s][dc] = *(const uint4*)(Q  + (size_t)(bm + s) * HDd + dc);
        *(uint4*)&Ks_[s][dc] = *(const uint4*)(Kp + (size_t)(bn + s) * HDd + dc);
    }
    __syncthreads();

#pragma unroll
    for (int ks = 0; ks < 64; ks += 16) {
        uint32_t af[4][4], bf[4][2];
#pragma unroll
        for (int mt = 0; mt < 4; ++mt) {
            int r = warpM + mt * 16 + g;
            af[mt][0] = *(uint32_t*)&Qs_[r][ks + 2*tg];
            af[mt][1] = *(uint32_t*)&Qs_[r + 8][ks + 2*tg];
            af[mt][2] = *(uint32_t*)&Qs_[r][ks + 2*tg + 8];
            af[mt][3] = *(uint32_t*)&Qs_[r + 8][ks + 2*tg + 8];
        }
#pragma unroll
        for (int nt = 0; nt < 4; ++nt) {
            int c = warpN + nt * 8 + g;
            bf[nt][0] = *(uint32_t*)&Ks_[c][ks + 2*tg];
            bf[nt][1] = *(uint32_t*)&Ks_[c][ks + 2*tg + 8];
        }
#pragma unroll
        for (int mt = 0; mt < 4; ++mt)
#pragma unroll
            for (int nt = 0; nt < 4; ++nt)
                mma_f16(acc[mt][nt], af[mt], bf[nt]);
    }

    float* out = g_Sc + (size_t)z * PLANE;
#pragma unroll
    for (int mt = 0; mt < 4; ++mt)
#pragma unroll
        for (int nt = 0; nt < 4; ++nt) {
            int r0 = bm + warpM + mt * 16 + g;
            int c0 = bn + warpN + nt * 8 + 2 * tg;
            float2 v0 = {0.125f*acc[mt][nt][0], 0.125f*acc[mt][nt][1]};
            float2 v1 = {0.125f*acc[mt][nt][2], 0.125f*acc[mt][nt][3]};
            *(float2*)(out + (size_t)r0 * Ss + c0) = v0;
            *(float2*)(out + (size_t)(r0 + 8) * Ss + c0) = v1;
        }
}

// ---------------------------------------------------------------------------
// Softmax over HEAD axis. Reads raw fp32 scores; writes fp32 probs (output)
// and fp16 normalized P planes (g_P) for attn*V.
// ---------------------------------------------------------------------------
__global__ __launch_bounds__(256) void softmax_kernel(float* __restrict__ probs)
{
    int i = blockIdx.x * 256 + threadIdx.x;
    int n = i & 2047;
    int l = (i >> 11) & 2047;
    int b = i >> 22;
    size_t off = (size_t)l * Ss + n;

    float s[16];
#pragma unroll
    for (int h = 0; h < 16; ++h)
        s[h] = g_Sc[(size_t)(b*16 + h) * PLANE + off];

    float m = s[0];
#pragma unroll
    for (int h = 1; h < 16; ++h) m = fmaxf(m, s[h]);
    float sum = 0.f;
#pragma unroll
    for (int h = 0; h < 16; ++h) { s[h] = __expf(s[h] - m); sum += s[h]; }
    float r = 1.0f / sum;

    float* po = probs + (size_t)i * 16;
#pragma unroll
    for (int h4 = 0; h4 < 16; h4 += 4) {
        float4 o = {s[h4]*r, s[h4+1]*r, s[h4+2]*r, s[h4+3]*r};
        *(float4*)(po + h4) = o;
    }
#pragma unroll
    for (int h = 0; h < 16; ++h)
        g_P[(size_t)(b*16 + h) * PLANE + off] = __float2half_rn(s[h] * r);
}

// ---------------------------------------------------------------------------
// Attn*V (f16): per plane z: O[l,d] = sum_n P[l,n] * V[n,d]
// M=128-tile, N=64, K=2048, BK=32. V transposed to [d][n] at smem store.
// Writes g_A interleaved [b][s][h*64+d] fp16.
// ---------------------------------------------------------------------------
__global__ __launch_bounds__(256) void attnv_f16()
{
    __shared__ __half Ps_[128][40];   // [l][n]
    __shared__ __half Vs_[64][40];    // [d][n]
    const int tid  = threadIdx.x;
    const int lane = tid & 31, w = tid >> 5;
    const int g = lane >> 2, tg = lane & 3;
    const int z  = blockIdx.y;
    const int bm = blockIdx.x * 128;
    const int warpM = (w >> 1) * 32, warpN = (w & 1) * 32;
    const __half* P = g_P + (size_t)z * PLANE;
    const __half* V = g_Vh + (size_t)z * (Ss*HDd);
    const int bz = z >> 4, hz = z & 15;
    __half* O = g_A + ((size_t)bz * 2048) * 1024 + hz * 64;

    float acc[2][4][4];
#pragma unroll
    for (int mt = 0; mt < 2; ++mt)
#pragma unroll
        for (int nt = 0; nt < 4; ++nt)
#pragma unroll
            for (int i = 0; i < 4; ++i) acc[mt][nt][i] = 0.f;

    uint4 pp[2], pv;
    {
#pragma unroll
        for (int it = 0; it < 2; ++it) {
            int ch = tid + it * 256;
            int m = ch >> 2, kc = (ch & 3) << 3;
            pp[it] = *(const uint4*)(P + (size_t)(bm + m) * Ss + kc);
        }
        int vn = tid >> 3, vdc = (tid & 7) << 3;
        pv = *(const uint4*)(V + (size_t)vn * HDd + vdc);
    }
#pragma unroll
    for (int it = 0; it < 2; ++it) {
        int ch = tid + it * 256;
        int m = ch >> 2, kc = (ch & 3) << 3;
        *(uint4*)&Ps_[m][kc] = pp[it];
    }
    {
        int vn = tid >> 3, vdc = (tid & 7) << 3;
        H8 t; t.u = pv;
#pragma unroll
        for (int j = 0; j < 8; ++j) Vs_[vdc + j][vn] = t.h[j];
    }
    __syncthreads();

    for (int k0 = 32; k0 <= Ss; k0 += 32) {
        if (k0 < Ss) {
#pragma unroll
            for (int it = 0; it < 2; ++it) {
                int ch = tid + it * 256;
                int m = ch >> 2, kc = (ch & 3) << 3;
                pp[it] = *(const uint4*)(P + (size_t)(bm + m) * Ss + k0 + kc);
            }
            int vn = tid >> 3, vdc = (tid & 7) << 3;
            pv = *(const uint4*)(V + (size_t)(k0 + vn) * HDd + vdc);
        }
#pragma unroll
        for (int ks = 0; ks < 32; ks += 16) {
            uint32_t af[2][4], bf[4][2];
#pragma unroll
            for (int mt = 0; mt < 2; ++mt) {
                int r = warpM + mt * 16 + g;
                af[mt][0] = *(uint32_t*)&Ps_[r][ks + 2*tg];
                af[mt][1] = *(uint32_t*)&Ps_[r + 8][ks + 2*tg];
                af[mt][2] = *(uint32_t*)&Ps_[r][ks + 2*tg + 8];
                af[mt][3] = *(uint32_t*)&Ps_[r + 8][ks + 2*tg + 8];
            }
#pragma unroll
            for (int nt = 0; nt < 4; ++nt) {
                int c = warpN + nt * 8 + g;
                bf[nt][0] = *(uint32_t*)&Vs_[c][ks + 2*tg];
                bf[nt][1] = *(uint32_t*)&Vs_[c][ks + 2*tg + 8];
            }
#pragma unroll
            for (int mt = 0; mt < 2; ++mt)
#pragma unroll
                for (int nt = 0; nt < 4; ++nt)
                    mma_f16(acc[mt][nt], af[mt], bf[nt]);
        }
        if (k0 < Ss) {
            __syncthreads();
#pragma unroll
            for (int it = 0; it < 2; ++it) {
                int ch = tid + it * 256;
                int m = ch >> 2, kc = (ch & 3) << 3;
                *(uint4*)&Ps_[m][kc] = pp[it];
            }
            int vn = tid >> 3, vdc = (tid & 7) << 3;
            H8 t; t.u = pv;
#pragma unroll
            for (int j = 0; j < 8; ++j) Vs_[vdc + j][vn] = t.h[j];
            __syncthreads();
        }
    }
#pragma unroll
    for (int mt = 0; mt < 2; ++mt)
#pragma unroll
        for (int nt = 0; nt < 4; ++nt) {
            int r0 = bm + warpM + mt * 16 + g;      // s
            int c0 = warpN + nt * 8 + 2 * tg;       // d
            *(__half2*)(O + (size_t)r0 * 1024 + c0) =
                __floats2half2_rn(acc[mt][nt][0], acc[mt][nt][1]);
            *(__half2*)(O + (size_t)(r0 + 8) * 1024 + c0) =
                __floats2half2_rn(acc[mt][nt][2], acc[mt][nt][3]);
        }
}

// ---------------------------------------------------------------------------
extern "C" void kernel_launch(void* const* d_in, const int* in_sizes, int n_in,
                              void* d_out, int out_size)
{
    const float* query = (const float*)d_in[0];
    const float* key   = (const float*)d_in[1];
    const float* value = (const float*)d_in[2];
    const float* Wq = (const float*)d_in[3];  const float* bq = (const float*)d_in[4];
    const float* Wk = (const float*)d_in[5];  const float* bk = (const float*)d_in[6];
    const float* Wv = (const float*)d_in[7];  const float* bv = (const float*)d_in[8];
    const float* Wo = (const float*)d_in[9];  const float* bo = (const float*)d_in[10];

    float* out   = (float*)d_out;
    float* probs = out + BSD;

    void* p;
    cudaGetSymbolAddress(&p, g_Wq); __half* gWq = (__half*)p;
    cudaGetSymbolAddress(&p, g_Wk); __half* gWk = (__half*)p;
    cudaGetSymbolAddress(&p, g_Wv); __half* gWv = (__half*)p;
    cudaGetSymbolAddress(&p, g_Wo); __half* gWo = (__half*)p;
    cudaGetSymbolAddress(&p, g_bp); float*  gbp = (float*)p;
    cudaGetSymbolAddress(&p, g_Qh); __half* gQh = (__half*)p;
    cudaGetSymbolAddress(&p, g_Kh); __half* gKh = (__half*)p;
    cudaGetSymbolAddress(&p, g_Vh); __half* gVh = (__half*)p;
    cudaGetSymbolAddress(&p, g_A);  __half* gA  = (__half*)p;

    dim3 gemm_grid(Dd/128, MM/128);   // (8, 32)

    // 0) Weight/bias permutations (fp16, transposed)
    perm_wT<<<64, 256>>>(Wq, gWq);
    perm_wT<<<64, 256>>>(Wk, gWk);
    perm_wT<<<64, 256>>>(Wv, gWv);
    perm_woT<<<64, 256>>>(Wo, gWo);
    perm_bias<<<12, 256>>>(bq, bk, bv, gbp);

    // 1) Projections -> fp16 head layout
    gemm_f16_headout<<<gemm_grid, 256>>>(query, gWq, gbp,        gQh);
    gemm_f16_headout<<<gemm_grid, 256>>>(key,   gWk, gbp + 1024, gKh);
    gemm_f16_headout<<<gemm_grid, 256>>>(value, gWv, gbp + 2048, gVh);

    // 2) Per-head raw scores (fp32) into g_Sc
    scores_f16<<<dim3(Ss/128, Ss/128, Bb*NHh), 256>>>();

    // 3) Softmax over heads: fp32 probs output + fp16 P planes
    softmax_kernel<<<(Bb*(size_t)Ss*Ss)/256, 256>>>(probs);

    // 4) Attn*V (fp16) -> interleaved fp16 activations
    attnv_f16<<<dim3(Ss/128, Bb*NHh), 256>>>();

    // 5) Output projection (fp16 inputs, fp32 out)
    gemm_f16_bias<<<gemm_grid, 256>>>(gA, gWo, bo, out);
}